// round 1
// baseline (speedup 1.0000x reference)
#include <cuda_runtime.h>
#include <cuda_bf16.h>

// Fused GraphSAGE layer:
//   agg[n]  = (sum_s features[neigh[n,s]] + features[node[n]]) / (S+1)
//   out[n]  = l2norm(relu(agg[n] @ W + b))
//
// One block = 32 nodes. Phases: gather->smem, register-tiled fp32 GEMM,
// fused bias/relu/l2norm epilogue.

#define BM      32
#define DDIM    256
#define THREADS 256
#define MAX_S   65   // supports n_samp+1 up to 65

__global__ __launch_bounds__(THREADS, 2)
void gsage_fused_kernel(const int*   __restrict__ node_idx,
                        const int*   __restrict__ neigh_idx,
                        const float* __restrict__ features,
                        const float* __restrict__ W,
                        const float* __restrict__ b,
                        float*       __restrict__ out,
                        int n_nodes, int n_samp)
{
    __shared__ float As[BM][DDIM];      // 32 KB: agg tile, reused as output tile
    __shared__ int   idxS[BM * MAX_S];  // gather indices for this block
    __shared__ float invN[BM];          // per-row 1/norm

    const int tid       = threadIdx.x;
    const int blockBase = blockIdx.x * BM;
    const int rows      = min(BM, n_nodes - blockBase);
    const int S         = n_samp + 1;

    // ---- stage indices: slot 0 = self, slots 1..n_samp = neighbors ----
    for (int i = tid; i < rows * S; i += THREADS) {
        int n = i / S, s = i - n * S;
        int gn = blockBase + n;
        idxS[n * S + s] = (s == 0) ? node_idx[gn]
                                   : neigh_idx[(long)gn * n_samp + (s - 1)];
    }
    __syncthreads();

    // ---- gather + mean: thread tid owns column tid ----
    const float invS = 1.0f / (float)S;
    for (int n = 0; n < BM; ++n) {
        float acc = 0.0f;
        if (n < rows) {
            const int* ip = &idxS[n * S];
            #pragma unroll 8
            for (int s = 0; s < S; ++s) {
                long off = (long)ip[s] * DDIM + tid;
                acc += __ldg(features + off);
            }
        }
        As[n][tid] = acc * invS;   // zero for padded rows
    }
    __syncthreads();

    // ---- register-tiled GEMM: 8 rows x 4 cols per thread ----
    const int cthread = tid & 63;   // 0..63 -> cols cthread*4 .. +3
    const int rthread = tid >> 6;   // 0..3  -> rows rthread*8 .. +7
    const int rowBase = rthread * 8;

    float accum[8][4];
    #pragma unroll
    for (int r = 0; r < 8; ++r)
        #pragma unroll
        for (int c = 0; c < 4; ++c) accum[r][c] = 0.0f;

    const float4* W4 = reinterpret_cast<const float4*>(W);
    #pragma unroll 4
    for (int k = 0; k < DDIM; ++k) {
        float4 w = __ldg(&W4[k * (DDIM / 4) + cthread]);
        float a[8];
        #pragma unroll
        for (int r = 0; r < 8; ++r) a[r] = As[rowBase + r][k];  // warp-broadcast
        #pragma unroll
        for (int r = 0; r < 8; ++r) {
            accum[r][0] = fmaf(a[r], w.x, accum[r][0]);
            accum[r][1] = fmaf(a[r], w.y, accum[r][1]);
            accum[r][2] = fmaf(a[r], w.z, accum[r][2]);
            accum[r][3] = fmaf(a[r], w.w, accum[r][3]);
        }
    }

    // ---- epilogue: bias + relu, stash back into smem ----
    const float4 bias = __ldg(&reinterpret_cast<const float4*>(b)[cthread]);
    __syncthreads();   // everyone done reading As before overwrite
    #pragma unroll
    for (int r = 0; r < 8; ++r) {
        float4 v;
        v.x = fmaxf(accum[r][0] + bias.x, 0.0f);
        v.y = fmaxf(accum[r][1] + bias.y, 0.0f);
        v.z = fmaxf(accum[r][2] + bias.z, 0.0f);
        v.w = fmaxf(accum[r][3] + bias.w, 0.0f);
        reinterpret_cast<float4*>(&As[rowBase + r][0])[cthread] = v;
    }
    __syncthreads();

    // ---- per-row L2 norm: warp w handles rows 4w..4w+3 ----
    const int wid = tid >> 5, lane = tid & 31;
    #pragma unroll
    for (int rr = 0; rr < 4; ++rr) {
        int row = wid * 4 + rr;
        float s = 0.0f;
        #pragma unroll
        for (int j = 0; j < 8; ++j) {       // stride-32: conflict-free
            float v = As[row][lane + 32 * j];
            s = fmaf(v, v, s);
        }
        #pragma unroll
        for (int o = 16; o > 0; o >>= 1)
            s += __shfl_xor_sync(0xffffffffu, s, o);
        if (lane == 0)
            invN[row] = 1.0f / fmaxf(sqrtf(s), 1e-12f);
    }
    __syncthreads();

    // ---- normalized vectorized store ----
    float4* out4 = reinterpret_cast<float4*>(out);
    const float4* Os4 = reinterpret_cast<const float4*>(&As[0][0]);
    for (int i = tid; i < BM * (DDIM / 4); i += THREADS) {
        int r = i >> 6;                 // DDIM/4 == 64 cols of float4
        if (r < rows) {
            float4 v = Os4[i];
            float sc = invN[r];
            v.x *= sc; v.y *= sc; v.z *= sc; v.w *= sc;
            out4[(long)(blockBase + r) * (DDIM / 4) + (i & 63)] = v;
        }
    }
}

extern "C" void kernel_launch(void* const* d_in, const int* in_sizes, int n_in,
                              void* d_out, int out_size)
{
    const int*   node_idx  = (const int*)  d_in[0];
    const int*   neigh_idx = (const int*)  d_in[1];
    const float* features  = (const float*)d_in[2];
    const float* W         = (const float*)d_in[3];
    const float* b         = (const float*)d_in[4];
    float*       out       = (float*)      d_out;

    const int n_nodes = in_sizes[0];
    const int n_samp  = in_sizes[1] / n_nodes;   // 32

    const int grid = (n_nodes + BM - 1) / BM;
    gsage_fused_kernel<<<grid, THREADS>>>(node_idx, neigh_idx, features, W, b,
                                          out, n_nodes, n_samp);
}

// round 2
// speedup vs baseline: 2.1266x; 2.1266x over previous
#include <cuda_runtime.h>
#include <cuda_bf16.h>

// Fused GraphSAGE layer:
//   agg[n]  = (sum_s features[neigh[n,s]] + features[node[n]]) / (S+1)
//   out[n]  = l2norm(relu(agg[n] @ W + b))
//
// One block = 32 nodes, 512 threads, 2 blocks/SM (32 warps).
// Phase 1: float4 gather with 4 independent node accumulators per thread.
// Phase 2: register-tiled fp32 GEMM (4x4 per thread), LDS.128 A reads.
// Phase 3: bias/relu/l2norm epilogue fused.

#define BM      32
#define DDIM    256
#define THREADS 512
#define MAX_S   40   // supports n_samp+1 up to 40

__global__ __launch_bounds__(THREADS, 2)
void gsage_fused_kernel(const int*   __restrict__ node_idx,
                        const int*   __restrict__ neigh_idx,
                        const float* __restrict__ features,
                        const float* __restrict__ W,
                        const float* __restrict__ b,
                        float*       __restrict__ out,
                        int n_nodes, int n_samp)
{
    __shared__ float As[BM][DDIM];      // 32 KB: agg tile, reused as output tile
    __shared__ int   idxS[BM * MAX_S];  // gather indices
    __shared__ float invN[BM];          // per-row 1/norm

    const int tid       = threadIdx.x;
    const int blockBase = blockIdx.x * BM;
    const int rows      = min(BM, n_nodes - blockBase);
    const int S         = n_samp + 1;

    // ---- stage indices: slot 0 = self, slots 1..n_samp = neighbors ----
    for (int i = tid; i < rows * S; i += THREADS) {
        int n = i / S, s = i - n * S;
        int gn = blockBase + n;
        idxS[n * S + s] = (s == 0) ? node_idx[gn]
                                   : neigh_idx[(long)gn * n_samp + (s - 1)];
    }
    __syncthreads();

    // ---- gather + mean: float4 columns, 4 nodes per thread ----
    // c4 = float4 column (0..63), grp = node group (0..7) -> nodes grp*4..+3
    {
        const int c4  = tid & 63;
        const int grp = tid >> 6;
        const int n0  = grp * 4;
        const float4* F4 = reinterpret_cast<const float4*>(features);

        const bool v0 = (n0 + 0) < rows;
        const bool v1 = (n0 + 1) < rows;
        const bool v2 = (n0 + 2) < rows;
        const bool v3 = (n0 + 3) < rows;
        const int* ip0 = idxS + (v0 ? (n0 + 0) * S : 0);
        const int* ip1 = idxS + (v1 ? (n0 + 1) * S : 0);
        const int* ip2 = idxS + (v2 ? (n0 + 2) * S : 0);
        const int* ip3 = idxS + (v3 ? (n0 + 3) * S : 0);

        float4 a0 = {0,0,0,0}, a1 = {0,0,0,0}, a2 = {0,0,0,0}, a3 = {0,0,0,0};

        #pragma unroll 2
        for (int s = 0; s < S; ++s) {
            float4 t0 = __ldg(F4 + (long)ip0[s] * (DDIM/4) + c4);
            float4 t1 = __ldg(F4 + (long)ip1[s] * (DDIM/4) + c4);
            float4 t2 = __ldg(F4 + (long)ip2[s] * (DDIM/4) + c4);
            float4 t3 = __ldg(F4 + (long)ip3[s] * (DDIM/4) + c4);
            a0.x += t0.x; a0.y += t0.y; a0.z += t0.z; a0.w += t0.w;
            a1.x += t1.x; a1.y += t1.y; a1.z += t1.z; a1.w += t1.w;
            a2.x += t2.x; a2.y += t2.y; a2.z += t2.z; a2.w += t2.w;
            a3.x += t3.x; a3.y += t3.y; a3.z += t3.z; a3.w += t3.w;
        }

        const float invS = 1.0f / (float)S;
        float m0 = v0 ? invS : 0.0f, m1 = v1 ? invS : 0.0f;
        float m2 = v2 ? invS : 0.0f, m3 = v3 ? invS : 0.0f;
        a0.x *= m0; a0.y *= m0; a0.z *= m0; a0.w *= m0;
        a1.x *= m1; a1.y *= m1; a1.z *= m1; a1.w *= m1;
        a2.x *= m2; a2.y *= m2; a2.z *= m2; a2.w *= m2;
        a3.x *= m3; a3.y *= m3; a3.z *= m3; a3.w *= m3;

        reinterpret_cast<float4*>(&As[n0 + 0][0])[c4] = a0;
        reinterpret_cast<float4*>(&As[n0 + 1][0])[c4] = a1;
        reinterpret_cast<float4*>(&As[n0 + 2][0])[c4] = a2;
        reinterpret_cast<float4*>(&As[n0 + 3][0])[c4] = a3;
    }
    __syncthreads();

    // ---- register-tiled GEMM: 4 rows x 4 cols per thread ----
    const int ct = tid & 63;   // cols ct*4 .. +3
    const int rt = tid >> 6;   // rows rt*4 .. +3
    const int rowBase = rt * 4;

    float acc[4][4];
    #pragma unroll
    for (int r = 0; r < 4; ++r)
        #pragma unroll
        for (int c = 0; c < 4; ++c) acc[r][c] = 0.0f;

    const float4* W4 = reinterpret_cast<const float4*>(W);
    #pragma unroll 2
    for (int k = 0; k < DDIM; k += 4) {
        // 4 consecutive k of A per row, one LDS.128 each (warp-broadcast)
        float4 aq[4];
        #pragma unroll
        for (int r = 0; r < 4; ++r)
            aq[r] = *reinterpret_cast<const float4*>(&As[rowBase + r][k]);
        // W rows k..k+3, 4 cols each
        float4 w0 = __ldg(&W4[(k + 0) * (DDIM/4) + ct]);
        float4 w1 = __ldg(&W4[(k + 1) * (DDIM/4) + ct]);
        float4 w2 = __ldg(&W4[(k + 2) * (DDIM/4) + ct]);
        float4 w3 = __ldg(&W4[(k + 3) * (DDIM/4) + ct]);

        #pragma unroll
        for (int r = 0; r < 4; ++r) {
            acc[r][0] = fmaf(aq[r].x, w0.x, acc[r][0]);
            acc[r][1] = fmaf(aq[r].x, w0.y, acc[r][1]);
            acc[r][2] = fmaf(aq[r].x, w0.z, acc[r][2]);
            acc[r][3] = fmaf(aq[r].x, w0.w, acc[r][3]);

            acc[r][0] = fmaf(aq[r].y, w1.x, acc[r][0]);
            acc[r][1] = fmaf(aq[r].y, w1.y, acc[r][1]);
            acc[r][2] = fmaf(aq[r].y, w1.z, acc[r][2]);
            acc[r][3] = fmaf(aq[r].y, w1.w, acc[r][3]);

            acc[r][0] = fmaf(aq[r].z, w2.x, acc[r][0]);
            acc[r][1] = fmaf(aq[r].z, w2.y, acc[r][1]);
            acc[r][2] = fmaf(aq[r].z, w2.z, acc[r][2]);
            acc[r][3] = fmaf(aq[r].z, w2.w, acc[r][3]);

            acc[r][0] = fmaf(aq[r].w, w3.x, acc[r][0]);
            acc[r][1] = fmaf(aq[r].w, w3.y, acc[r][1]);
            acc[r][2] = fmaf(aq[r].w, w3.z, acc[r][2]);
            acc[r][3] = fmaf(aq[r].w, w3.w, acc[r][3]);
        }
    }

    // ---- epilogue: bias + relu into smem ----
    const float4 bias = __ldg(&reinterpret_cast<const float4*>(b)[ct]);
    __syncthreads();   // everyone done reading As before overwrite
    #pragma unroll
    for (int r = 0; r < 4; ++r) {
        float4 v;
        v.x = fmaxf(acc[r][0] + bias.x, 0.0f);
        v.y = fmaxf(acc[r][1] + bias.y, 0.0f);
        v.z = fmaxf(acc[r][2] + bias.z, 0.0f);
        v.w = fmaxf(acc[r][3] + bias.w, 0.0f);
        reinterpret_cast<float4*>(&As[rowBase + r][0])[ct] = v;
    }
    __syncthreads();

    // ---- per-row L2 norm: warp w handles rows 2w, 2w+1 ----
    const int wid = tid >> 5, lane = tid & 31;
    #pragma unroll
    for (int rr = 0; rr < 2; ++rr) {
        int row = wid * 2 + rr;
        float s = 0.0f;
        #pragma unroll
        for (int j = 0; j < 8; ++j) {       // stride-32: conflict-free
            float v = As[row][lane + 32 * j];
            s = fmaf(v, v, s);
        }
        #pragma unroll
        for (int o = 16; o > 0; o >>= 1)
            s += __shfl_xor_sync(0xffffffffu, s, o);
        if (lane == 0)
            invN[row] = 1.0f / fmaxf(sqrtf(s), 1e-12f);
    }
    __syncthreads();

    // ---- normalized vectorized store ----
    float4* out4 = reinterpret_cast<float4*>(out);
    const float4* Os4 = reinterpret_cast<const float4*>(&As[0][0]);
    #pragma unroll
    for (int i = tid; i < BM * (DDIM / 4); i += THREADS) {
        int r = i >> 6;                 // 64 float4 per row
        if (r < rows) {
            float4 v = Os4[i];
            float sc = invN[r];
            v.x *= sc; v.y *= sc; v.z *= sc; v.w *= sc;
            out4[(long)(blockBase + r) * (DDIM / 4) + (i & 63)] = v;
        }
    }
}

extern "C" void kernel_launch(void* const* d_in, const int* in_sizes, int n_in,
                              void* d_out, int out_size)
{
    const int*   node_idx  = (const int*)  d_in[0];
    const int*   neigh_idx = (const int*)  d_in[1];
    const float* features  = (const float*)d_in[2];
    const float* W         = (const float*)d_in[3];
    const float* b         = (const float*)d_in[4];
    float*       out       = (float*)      d_out;

    const int n_nodes = in_sizes[0];
    const int n_samp  = in_sizes[1] / n_nodes;   // 32

    const int grid = (n_nodes + BM - 1) / BM;
    gsage_fused_kernel<<<grid, THREADS>>>(node_idx, neigh_idx, features, W, b,
                                          out, n_nodes, n_samp);
}